// round 13
// baseline (speedup 1.0000x reference)
#include <cuda_runtime.h>
#include <cuda_fp16.h>
#include <cuda_bf16.h>

// Problem constants
#define Bn 4
#define Cn 64
#define Hn 96
#define Wn 96
#define PLANE (Hn*Wn)            // 9216
#define NPLANES (Bn*Cn)          // 256
#define NTOT (NPLANES*PLANE)     // 2359296
#define CNT_PER_CH (Bn*PLANE)    // 36864
#define BN_EPS 1e-5f
#define NPART 36                 // partial sums per channel: Bn * (3x3 blocks)

// Scratch (__device__ globals; allocation-free rule)
__device__ float g_y[NTOT];
__device__ float g_psum[Cn * NPART];
__device__ float g_psq [Cn * NPART];

__device__ __forceinline__ float silu_f(float x) {
    return __fdividef(x, 1.0f + __expf(-x));
}

// ---------------------------------------------------------------------------
// Kernel 1: KAN depthwise conv, base term folded into the spline table.
// grid = (3, 3, 256 planes), block = 256 (32 x 8), 4 strided rows/thread.
// Tile entry is ONE 4B word: (m*72)<<16 | u16, u16 = frac * 65536.
// Per tap: LDS.32 + LDS.64 + decode + 3 FMA + FADD  (3 crossbar wavefronts).
// ---------------------------------------------------------------------------
__global__ __launch_bounds__(256)
void kan_conv_kernel(const float* __restrict__ x,
                     const float* __restrict__ base_weight,    // (9)
                     const float* __restrict__ spline_weight,  // (9,8)
                     const float* __restrict__ spline_scaler)  // (9)
{
    __shared__ unsigned s_t[34 * 35];      // packed (mo<<16 | u16), pitch 35
    __shared__ uint2    s_coef[12 * 9];    // half2(c0,c1), half2(c2,c3)
    __shared__ float    s_rs[8], s_rq[8];

    const int tid   = threadIdx.x;
    const int plane = blockIdx.z;
    const int ty0   = blockIdx.y * 32;
    const int tx0   = blockIdx.x * 32;

    // ---- build coefficient table: uniform cubic B-spline (closed form)
    //      + Hermite cubic of bw[k]*silu(x) on each interval.
    //      Sentinel row m=11 (out-of-range x): tile stores w=(silu+1)/8,
    //      row coefs encode poly(w)=bw*(8w-1) -> exact base term.
    if (tid < 108) {
        const int m = tid / 9, k = tid % 9;
        const float bwk = base_weight[k];
        float c0, c1, c2, c3;
        if (m < 11) {
            c0 = c1 = c2 = c3 = 0.f;
            const float F[4][4] = {
                {1.f, -3.f,  3.f, -1.f},
                {4.f,  0.f, -6.f,  3.f},
                {1.f,  3.f,  3.f, -3.f},
                {0.f,  0.f,  0.f,  1.f}
            };
            const float sc = spline_scaler[k] * (1.0f / 6.0f);
            #pragma unroll
            for (int r = 0; r < 4; r++) {
                int j = m - 3 + r;
                if (j >= 0 && j < 8) {
                    float w = spline_weight[k * 8 + j] * sc;
                    c0 += w * F[r][0]; c1 += w * F[r][1];
                    c2 += w * F[r][2]; c3 += w * F[r][3];
                }
            }
            const float x0 = -2.2f + 0.4f * (float)m;
            const float x1 = x0 + 0.4f;
            const float f0 = silu_f(x0), f1 = silu_f(x1);
            const float sg0 = 1.0f / (1.0f + __expf(-x0));
            const float sg1 = 1.0f / (1.0f + __expf(-x1));
            const float d0 = 0.4f * sg0 * (1.0f + x0 * (1.0f - sg0));
            const float d1 = 0.4f * sg1 * (1.0f + x1 * (1.0f - sg1));
            c0 += bwk * f0;
            c1 += bwk * d0;
            c2 += bwk * (3.0f * (f1 - f0) - 2.0f * d0 - d1);
            c3 += bwk * (2.0f * (f0 - f1) + d0 + d1);
        } else {
            c0 = -bwk; c1 = 8.0f * bwk; c2 = 0.f; c3 = 0.f;
        }
        __half2 h01 = __floats2half2_rn(c0, c1);
        __half2 h23 = __floats2half2_rn(c2, c3);
        uint2 w;
        w.x = *reinterpret_cast<unsigned*>(&h01);
        w.y = *reinterpret_cast<unsigned*>(&h23);
        s_coef[m * 9 + k] = w;
    }

    // ---- load + transform + pack halo tile (34x34) ----
    const float* xp = x + plane * PLANE;
    for (int i = tid; i < 34 * 34; i += 256) {
        int hy = i / 34, hx = i % 34;
        int gy = ty0 + hy - 1, gx = tx0 + hx - 1;
        float v = (gy >= 0 && gy < Hn && gx >= 0 && gx < Wn) ? xp[gy * Wn + gx] : 0.0f;
        float mu = (v + 2.2f) * 2.5f;
        unsigned w;
        if (mu >= 0.0f && mu < 11.0f) {
            int m = (int)mu;
            unsigned u16 = (unsigned)((mu - (float)m) * 65536.0f);
            w = ((unsigned)(m * 72) << 16) | (u16 & 0xFFFFu);
        } else {
            float s = silu_f(v);
            unsigned u16 = (unsigned)((s + 1.0f) * (65536.0f / 8.0f));
            if (u16 > 65535u) u16 = 65535u;
            w = (792u << 16) | u16;                   // row 11
        }
        s_t[hy * 35 + hx] = w;
    }
    __syncthreads();

    // ---- compute 32x32 outputs (4 strided rows per thread) ----
    const int tx  = tid & 31;
    const int tyb = tid >> 5;
    float lsum = 0.f, lsq = 0.f;
    const char* cbase = (const char*)s_coef;

    #pragma unroll
    for (int r = 0; r < 4; r++) {
        const int oy = tyb + r * 8;
        float acc = 0.f;
        #pragma unroll
        for (int dy = 0; dy < 3; dy++) {
            #pragma unroll
            for (int dx = 0; dx < 3; dx++) {
                const int k = dy * 3 + dx;
                unsigned w = s_t[(oy + dy) * 35 + (tx + dx)];
                float u = (float)(w & 0xFFFFu) * (1.0f / 65536.0f);
                uint2 cw = *(const uint2*)(cbase + (w >> 16) + k * 8);
                float2 c01 = __half22float2(*reinterpret_cast<__half2*>(&cw.x));
                float2 c23 = __half22float2(*reinterpret_cast<__half2*>(&cw.y));
                acc += fmaf(u, fmaf(u, fmaf(u, c23.y, c23.x), c01.y), c01.x);
            }
        }
        g_y[plane * PLANE + (ty0 + oy) * Wn + (tx0 + tx)] = acc;
        lsum += acc;
        lsq  = fmaf(acc, acc, lsq);
    }

    // ---- block reduction -> race-free partial slot ----
    #pragma unroll
    for (int o = 16; o > 0; o >>= 1) {
        lsum += __shfl_down_sync(0xffffffffu, lsum, o);
        lsq  += __shfl_down_sync(0xffffffffu, lsq,  o);
    }
    if (tx == 0) { s_rs[tyb] = lsum; s_rq[tyb] = lsq; }
    __syncthreads();
    if (tid == 0) {
        float s = 0.f, q = 0.f;
        #pragma unroll
        for (int i = 0; i < 8; i++) { s += s_rs[i]; q += s_rq[i]; }
        const int c = plane & (Cn - 1);
        const int b = plane >> 6;
        const int slot = c * NPART + b * 9 + blockIdx.y * 3 + blockIdx.x;
        g_psum[slot] = s;
        g_psq [slot] = q;
    }

    // PDL: allow the dependent bn kernel to start ramping
    cudaTriggerProgrammaticLaunchCompletion();
}

// ---------------------------------------------------------------------------
// Kernel 2: BatchNorm (batch stats from partials) + ReLU  (PDL secondary)
// ---------------------------------------------------------------------------
__global__ __launch_bounds__(256)
void bn_relu_kernel(const float* __restrict__ gamma,
                    const float* __restrict__ beta,
                    float* __restrict__ out)
{
    const int plane = blockIdx.y;
    const int c     = plane & (Cn - 1);
    const int tid   = threadIdx.x;
    const int lane  = tid & 31;
    const int base  = plane * (PLANE / 4) + blockIdx.x * 768 + tid;
    const float gc  = gamma[c];              // independent of conv — prefetch
    const float bc  = beta[c];

    cudaGridDependencySynchronize();

    float s = g_psum[c * NPART + lane % NPART];
    float q = g_psq [c * NPART + lane % NPART];

    float4 v0 = reinterpret_cast<const float4*>(g_y)[base];
    float4 v1 = reinterpret_cast<const float4*>(g_y)[base + 256];
    float4 v2 = reinterpret_cast<const float4*>(g_y)[base + 512];

    if (lane < NPART - 32) {
        s += g_psum[c * NPART + lane + 32];
        q += g_psq [c * NPART + lane + 32];
    }
    #pragma unroll
    for (int o = 16; o > 0; o >>= 1) {
        s += __shfl_xor_sync(0xffffffffu, s, o);
        q += __shfl_xor_sync(0xffffffffu, q, o);
    }

    const float invN = 1.0f / (float)CNT_PER_CH;
    float mean = s * invN;
    float var  = q * invN - mean * mean;
    float scl  = rsqrtf(var + BN_EPS) * gc;
    float sh   = fmaf(-mean, scl, bc);

    float4 o0, o1, o2;
    o0.x = fmaxf(fmaf(v0.x, scl, sh), 0.0f);
    o0.y = fmaxf(fmaf(v0.y, scl, sh), 0.0f);
    o0.z = fmaxf(fmaf(v0.z, scl, sh), 0.0f);
    o0.w = fmaxf(fmaf(v0.w, scl, sh), 0.0f);
    o1.x = fmaxf(fmaf(v1.x, scl, sh), 0.0f);
    o1.y = fmaxf(fmaf(v1.y, scl, sh), 0.0f);
    o1.z = fmaxf(fmaf(v1.z, scl, sh), 0.0f);
    o1.w = fmaxf(fmaf(v1.w, scl, sh), 0.0f);
    o2.x = fmaxf(fmaf(v2.x, scl, sh), 0.0f);
    o2.y = fmaxf(fmaf(v2.y, scl, sh), 0.0f);
    o2.z = fmaxf(fmaf(v2.z, scl, sh), 0.0f);
    o2.w = fmaxf(fmaf(v2.w, scl, sh), 0.0f);
    reinterpret_cast<float4*>(out)[base]       = o0;
    reinterpret_cast<float4*>(out)[base + 256] = o1;
    reinterpret_cast<float4*>(out)[base + 512] = o2;
}

// ---------------------------------------------------------------------------
extern "C" void kernel_launch(void* const* d_in, const int* in_sizes, int n_in,
                              void* d_out, int out_size)
{
    const float* x             = (const float*)d_in[0];
    const float* base_weight   = (const float*)d_in[1];
    const float* spline_weight = (const float*)d_in[2];
    const float* spline_scaler = (const float*)d_in[3];
    const float* bn_gamma      = (const float*)d_in[4];
    const float* bn_beta       = (const float*)d_in[5];
    float* out                 = (float*)d_out;

    dim3 grid(3, 3, NPLANES);
    kan_conv_kernel<<<grid, 256>>>(x, base_weight, spline_weight, spline_scaler);

    // bn with Programmatic Dependent Launch: overlaps its ramp with conv tail
    cudaLaunchConfig_t cfg = {};
    cfg.gridDim  = dim3(3, NPLANES);
    cfg.blockDim = dim3(256);
    cfg.stream   = 0;
    cudaLaunchAttribute attrs[1];
    attrs[0].id = cudaLaunchAttributeProgrammaticStreamSerialization;
    attrs[0].val.programmaticStreamSerializationAllowed = 1;
    cfg.attrs    = attrs;
    cfg.numAttrs = 1;
    cudaLaunchKernelEx(&cfg, bn_relu_kernel, bn_gamma, bn_beta, out);
}